// round 3
// baseline (speedup 1.0000x reference)
#include <cuda_runtime.h>

#define NN   100000
#define EE   1600000
#define DIM  128
#define OUTD 64

// ---------------- scratch (device globals; no allocation allowed) ----------
__device__ float g_dinv[NN];
__device__ float g_acc [(size_t)NN * DIM];
__device__ float g_bufA[(size_t)NN * DIM];
__device__ float g_bufB[(size_t)NN * DIM];
__device__ float g_h0  [(size_t)NN * DIM];

// ---------------- degree / normalization ----------------------------------
__global__ void k_deg_init() {
    int i = blockIdx.x * blockDim.x + threadIdx.x;
    if (i < NN) g_dinv[i] = 1.0f;   // self loop contributes 1
}

__global__ void k_deg_count(const int* __restrict__ ei) {
    int i = blockIdx.x * blockDim.x + threadIdx.x;
    if (i < EE) atomicAdd(&g_dinv[ei[EE + i]], 1.0f);  // col histogram
}

__global__ void k_deg_fin() {
    int i = blockIdx.x * blockDim.x + threadIdx.x;
    if (i < NN) g_dinv[i] = rsqrtf(g_dinv[i]);   // deg >= 1 always
}

// ---------------- accumulator init: acc[n][c] = sum_i b[i][c] --------------
__global__ void k_acc_init(const float* __restrict__ b, float* __restrict__ acc) {
    int i = blockIdx.x * blockDim.x + threadIdx.x;
    if (i < NN * DIM) {
        int c = i & (DIM - 1);
        acc[i] = b[c] + b[DIM + c] + b[2 * DIM + c] + b[3 * DIM + c] + b[4 * DIM + c];
    }
}

// ---------------- hop: self-loop term (also initializes dst) ---------------
__global__ void k_selfloop(const float* __restrict__ src, float* __restrict__ dst) {
    int i = blockIdx.x * blockDim.x + threadIdx.x;   // over NN*32 float4s
    if (i >= NN * 32) return;
    int n = i >> 5;
    float d = g_dinv[n];
    d = d * d;
    float4 v = ((const float4*)src)[i];
    v.x *= d; v.y *= d; v.z *= d; v.w *= d;
    ((float4*)dst)[i] = v;
}

// ---------------- hop: edge scatter (one warp per edge) --------------------
__global__ void k_scatter(const float* __restrict__ src, float* __restrict__ dst,
                          const int* __restrict__ ei) {
    int w = (blockIdx.x * blockDim.x + threadIdx.x) >> 5;
    if (w >= EE) return;
    int lane = threadIdx.x & 31;
    int r = ei[w];        // row (source)
    int c = ei[EE + w];   // col (destination)
    float s = g_dinv[r] * g_dinv[c];
    float4 v = ((const float4*)(src + (size_t)r * DIM))[lane];
    float4* d = ((float4*)(dst + (size_t)c * DIM)) + lane;
    asm volatile("red.global.add.v4.f32 [%0], {%1, %2, %3, %4};"
                 :: "l"(d), "f"(s * v.x), "f"(s * v.y), "f"(s * v.z), "f"(s * v.w)
                 : "memory");
}

// ---------------- GEMM: C[M][128] += A[M][128] * B[128][128] ---------------
// BM=64, BN=128, BK=32, 256 threads, TM=4, TN=8
__global__ void __launch_bounds__(256) k_gemm_acc(const float* __restrict__ A,
                                                  const float* __restrict__ B,
                                                  float* __restrict__ C) {
    __shared__ float As[32][64];    // transposed A tile  (8 KB)
    __shared__ float Bs[32][128];   // B tile            (16 KB)
    int tid  = threadIdx.x;
    int tcol = tid & 15;    // 0..15 -> cols tcol*4 and 64+tcol*4
    int trow = tid >> 4;    // 0..15 -> rows trow*4..trow*4+3
    int m0   = blockIdx.x * 64;

    float acc[4][8];
#pragma unroll
    for (int m = 0; m < 4; m++)
#pragma unroll
        for (int n = 0; n < 8; n++) acc[m][n] = 0.0f;

    for (int k0 = 0; k0 < 128; k0 += 32) {
        // A tile, transposed store: 64 rows x 32 k = 512 float4 loads
#pragma unroll
        for (int l = 0; l < 2; l++) {
            int f  = tid + l * 256;     // 0..511
            int r  = f & 63;
            int kv = f >> 6;            // 0..7
            float4 v = make_float4(0.f, 0.f, 0.f, 0.f);
            int gr = m0 + r;
            if (gr < NN) v = *(const float4*)(A + (size_t)gr * DIM + k0 + kv * 4);
            As[kv * 4 + 0][r] = v.x;
            As[kv * 4 + 1][r] = v.y;
            As[kv * 4 + 2][r] = v.z;
            As[kv * 4 + 3][r] = v.w;
        }
        // B tile: 32 x 128 floats = 1024 float4
#pragma unroll
        for (int l = 0; l < 4; l++) {
            int f  = tid + l * 256;     // 0..1023
            int k  = f >> 5;            // 0..31
            int cv = f & 31;            // 0..31
            *(float4*)&Bs[k][cv * 4] = *(const float4*)(B + (size_t)(k0 + k) * DIM + cv * 4);
        }
        __syncthreads();

#pragma unroll
        for (int k = 0; k < 32; k++) {
            float4 a  = *(float4*)&As[k][trow * 4];
            float4 b0 = *(float4*)&Bs[k][tcol * 4];
            float4 b1 = *(float4*)&Bs[k][64 + tcol * 4];
            float am[4] = {a.x, a.y, a.z, a.w};
            float bn[8] = {b0.x, b0.y, b0.z, b0.w, b1.x, b1.y, b1.z, b1.w};
#pragma unroll
            for (int m = 0; m < 4; m++)
#pragma unroll
                for (int n = 0; n < 8; n++) acc[m][n] += am[m] * bn[n];
        }
        __syncthreads();
    }

    // write back: C += acc
#pragma unroll
    for (int m = 0; m < 4; m++) {
        int gr = m0 + trow * 4 + m;
        if (gr < NN) {
            float* row = C + (size_t)gr * DIM;
            float4 c0 = *(float4*)(row + tcol * 4);
            float4 c1 = *(float4*)(row + 64 + tcol * 4);
            c0.x += acc[m][0]; c0.y += acc[m][1]; c0.z += acc[m][2]; c0.w += acc[m][3];
            c1.x += acc[m][4]; c1.y += acc[m][5]; c1.z += acc[m][6]; c1.w += acc[m][7];
            *(float4*)(row + tcol * 4)      = c0;
            *(float4*)(row + 64 + tcol * 4) = c1;
        }
    }
}

// ---------------- relu store of graph-0 hidden -----------------------------
__global__ void k_relu_store() {
    int i = blockIdx.x * blockDim.x + threadIdx.x;   // over NN*32 float4s
    if (i >= NN * 32) return;
    float4 v = ((const float4*)g_acc)[i];
    v.x = fmaxf(v.x, 0.f); v.y = fmaxf(v.y, 0.f);
    v.z = fmaxf(v.z, 0.f); v.w = fmaxf(v.w, 0.f);
    ((float4*)g_h0)[i] = v;
}

// ---------------- fusion + classifier: out = (w0*h0 + w1*relu(acc)) @ Wc + bc
// BM=64, BN=64, BK=32, 256 threads, TM=4, TN=4
__global__ void __launch_bounds__(256) k_final(const float* __restrict__ fw,
                                               const float* __restrict__ Wc,
                                               const float* __restrict__ bc,
                                               float* __restrict__ out) {
    __shared__ float As[32][64];
    __shared__ float Bs[32][64];
    int tid  = threadIdx.x;
    int tcol = tid & 15;
    int trow = tid >> 4;
    int m0   = blockIdx.x * 64;

    float f0 = fw[0], f1 = fw[1];
    float mx = fmaxf(f0, f1);
    float e0 = __expf(f0 - mx), e1 = __expf(f1 - mx);
    float w0 = e0 / (e0 + e1), w1 = 1.0f - w0;

    float acc[4][4];
#pragma unroll
    for (int m = 0; m < 4; m++)
#pragma unroll
        for (int n = 0; n < 4; n++) acc[m][n] = 0.0f;

    for (int k0 = 0; k0 < 128; k0 += 32) {
        // fused A tile (transposed)
#pragma unroll
        for (int l = 0; l < 2; l++) {
            int f  = tid + l * 256;
            int r  = f & 63;
            int kv = f >> 6;
            float4 h = make_float4(0.f, 0.f, 0.f, 0.f);
            int gr = m0 + r;
            if (gr < NN) {
                size_t off = (size_t)gr * DIM + k0 + kv * 4;
                float4 h0 = *(const float4*)(g_h0 + off);
                float4 a  = *(const float4*)(g_acc + off);
                h.x = w0 * h0.x + w1 * fmaxf(a.x, 0.f);
                h.y = w0 * h0.y + w1 * fmaxf(a.y, 0.f);
                h.z = w0 * h0.z + w1 * fmaxf(a.z, 0.f);
                h.w = w0 * h0.w + w1 * fmaxf(a.w, 0.f);
            }
            As[kv * 4 + 0][r] = h.x;
            As[kv * 4 + 1][r] = h.y;
            As[kv * 4 + 2][r] = h.z;
            As[kv * 4 + 3][r] = h.w;
        }
        // Wc tile: 32 x 64 floats = 512 float4
#pragma unroll
        for (int l = 0; l < 2; l++) {
            int f  = tid + l * 256;
            int k  = f >> 4;          // 0..31
            int cv = f & 15;          // 0..15
            *(float4*)&Bs[k][cv * 4] = *(const float4*)(Wc + (size_t)(k0 + k) * OUTD + cv * 4);
        }
        __syncthreads();

#pragma unroll
        for (int k = 0; k < 32; k++) {
            float4 a = *(float4*)&As[k][trow * 4];
            float4 b = *(float4*)&Bs[k][tcol * 4];
            float am[4] = {a.x, a.y, a.z, a.w};
            float bn[4] = {b.x, b.y, b.z, b.w};
#pragma unroll
            for (int m = 0; m < 4; m++)
#pragma unroll
                for (int n = 0; n < 4; n++) acc[m][n] += am[m] * bn[n];
        }
        __syncthreads();
    }

    float4 bb = *(const float4*)(bc + tcol * 4);
#pragma unroll
    for (int m = 0; m < 4; m++) {
        int gr = m0 + trow * 4 + m;
        if (gr < NN) {
            float4 o;
            o.x = acc[m][0] + bb.x;
            o.y = acc[m][1] + bb.y;
            o.z = acc[m][2] + bb.z;
            o.w = acc[m][3] + bb.w;
            *(float4*)(out + (size_t)gr * OUTD + tcol * 4) = o;
        }
    }
}

// ---------------- host orchestration ---------------------------------------
extern "C" void kernel_launch(void* const* d_in, const int* in_sizes, int n_in,
                              void* d_out, int out_size) {
    const float* x      = (const float*)d_in[0];
    const int*   ei     = (const int*)d_in[1];
    const int*   gei    = (const int*)d_in[2];
    const float* w_orig = (const float*)d_in[3];
    const float* b_orig = (const float*)d_in[4];
    const float* w_aug  = (const float*)d_in[5];
    const float* b_aug  = (const float*)d_in[6];
    const float* fw     = (const float*)d_in[7];
    const float* clfw   = (const float*)d_in[8];
    const float* clfb   = (const float*)d_in[9];
    float*       out    = (float*)d_out;

    float *accp, *bufA, *bufB;
    cudaGetSymbolAddress((void**)&accp, g_acc);
    cudaGetSymbolAddress((void**)&bufA, g_bufA);
    cudaGetSymbolAddress((void**)&bufB, g_bufB);

    const int TB = 256;
    dim3 gN((NN + TB - 1) / TB);
    dim3 gE((EE + TB - 1) / TB);
    dim3 gV((NN * 32 + TB - 1) / TB);        // vector (float4) elementwise
    dim3 gA((NN * DIM + TB - 1) / TB);
    dim3 gS((EE + 7) / 8);                   // 8 warps/block, 1 warp/edge
    dim3 gG((NN + 63) / 64);                 // GEMM blocks

    for (int g = 0; g < 2; g++) {
        const int*   edges = g ? gei : ei;
        const float* W     = g ? w_aug : w_orig;
        const float* b     = g ? b_aug : b_orig;

        k_deg_init<<<gN, TB>>>();
        k_deg_count<<<gE, TB>>>(edges);
        k_deg_fin<<<gN, TB>>>();

        k_acc_init<<<gA, TB>>>(b, accp);
        k_gemm_acc<<<gG, TB>>>(x, W, accp);                     // order-0 term

        const float* src = x;
        float*       dst = bufA;
        for (int i = 1; i <= 4; i++) {
            k_selfloop<<<gV, TB>>>(src, dst);
            k_scatter<<<gS, TB>>>(src, dst, edges);
            k_gemm_acc<<<gG, TB>>>(dst, W + (size_t)i * DIM * DIM, accp);
            src = dst;
            dst = (dst == bufA) ? bufB : bufA;
        }

        if (g == 0) k_relu_store<<<gV, TB>>>();
    }

    k_final<<<gG, TB>>>(fw, clfw, clfb, out);
}

// round 4
// speedup vs baseline: 1.5629x; 1.5629x over previous
#include <cuda_runtime.h>

#define NN   100000
#define EE   1600000
#define DIM  128
#define OUTD 64
#define NB_SCAN 196   // ceil(NN/512)

// ---------------- scratch (device globals; no allocation allowed) ----------
__device__ float g_dinv[NN];
__device__ int   g_cnt[NN];
__device__ int   g_off[NN + 1];
__device__ int   g_cur[NN];
__device__ int   g_bsum[256];
__device__ int2  g_adj[EE];                  // (src_row, scale_as_float_bits)
__device__ float g_acc [(size_t)NN * DIM];
__device__ float g_bufA[(size_t)NN * DIM];
__device__ float g_bufB[(size_t)NN * DIM];
__device__ float g_h0  [(size_t)NN * DIM];

__device__ __forceinline__ float lo32(unsigned long long u) {
    return __uint_as_float((unsigned)u);
}
__device__ __forceinline__ float hi32(unsigned long long u) {
    return __uint_as_float((unsigned)(u >> 32));
}

// ---------------- degree -----------------------------------------------------
__global__ void k_deg_init() {
    int i = blockIdx.x * blockDim.x + threadIdx.x;
    if (i < NN) g_cnt[i] = 0;
}
__global__ void k_deg_count(const int* __restrict__ ei) {
    int i = blockIdx.x * blockDim.x + threadIdx.x;
    if (i < EE) atomicAdd(&g_cnt[ei[EE + i]], 1);
}
__global__ void k_deg_fin() {
    int i = blockIdx.x * blockDim.x + threadIdx.x;
    if (i < NN) g_dinv[i] = rsqrtf((float)g_cnt[i] + 1.0f);   // +1 self loop
}

// ---------------- exclusive scan of g_cnt -> g_off (3 kernels) ---------------
__global__ void k_scan1() {               // 512 threads per block
    __shared__ int s[512];
    int t = threadIdx.x;
    int i = blockIdx.x * 512 + t;
    int v = (i < NN) ? g_cnt[i] : 0;
    s[t] = v;
    __syncthreads();
#pragma unroll
    for (int off = 1; off < 512; off <<= 1) {
        int u = (t >= off) ? s[t - off] : 0;
        __syncthreads();
        s[t] += u;
        __syncthreads();
    }
    if (i < NN) { g_off[i] = s[t] - v; g_cur[i] = 0; }
    if (t == 511) g_bsum[blockIdx.x] = s[511];
}
__global__ void k_scan2() {               // 1 block, 256 threads
    __shared__ int s[256];
    int t = threadIdx.x;
    int v = (t < NB_SCAN) ? g_bsum[t] : 0;
    s[t] = v;
    __syncthreads();
#pragma unroll
    for (int off = 1; off < 256; off <<= 1) {
        int u = (t >= off) ? s[t - off] : 0;
        __syncthreads();
        s[t] += u;
        __syncthreads();
    }
    if (t < NB_SCAN) g_bsum[t] = s[t] - v;
}
__global__ void k_scan3() {
    int i = blockIdx.x * blockDim.x + threadIdx.x;
    if (i < NN) g_off[i] += g_bsum[i >> 9];
    if (i == 0) g_off[NN] = EE;
}

// ---------------- CSR fill ---------------------------------------------------
__global__ void k_fill(const int* __restrict__ ei) {
    int i = blockIdx.x * blockDim.x + threadIdx.x;
    if (i >= EE) return;
    int r = ei[i];
    int c = ei[EE + i];
    int pos = g_off[c] + atomicAdd(&g_cur[c], 1);
    float s = g_dinv[r] * g_dinv[c];
    g_adj[pos] = make_int2(r, __float_as_int(s));
}

// ---------------- hop: CSR pull (one warp per node, self-loop fused) ---------
__global__ void k_pull(const float* __restrict__ src, float* __restrict__ dst) {
    int w = (blockIdx.x * blockDim.x + threadIdx.x) >> 5;
    if (w >= NN) return;
    int lane = threadIdx.x & 31;
    int beg = g_off[w];
    int end = g_off[w + 1];
    float d = g_dinv[w];
    float dd = d * d;
    float4 acc = ((const float4*)(src + (size_t)w * DIM))[lane];
    acc.x *= dd; acc.y *= dd; acc.z *= dd; acc.w *= dd;
    for (int j = beg; j < end; j++) {
        int2 e = __ldg(&g_adj[j]);
        float s = __int_as_float(e.y);
        float4 v = ((const float4*)(src + (size_t)e.x * DIM))[lane];
        acc.x += s * v.x; acc.y += s * v.y;
        acc.z += s * v.z; acc.w += s * v.w;
    }
    ((float4*)(dst + (size_t)w * DIM))[lane] = acc;
}

// ---------------- GEMM (FFMA2): C[128-tile][128] (+)= A[*][128]*B[128][128] --
// BM=128, BN=128, BK=32, 256 threads, TM=8, TN=8 (4 packed f32x2 pairs)
// A stored pair-duplicated in smem so fma.rn.f32x2 operands load directly.
// bias != null: C initialized with sum of 5 bias rows (no C read).
__global__ void __launch_bounds__(256, 2) k_gemm_acc(const float* __restrict__ A,
                                                     const float* __restrict__ B,
                                                     float* __restrict__ C,
                                                     const float* __restrict__ bias) {
    __shared__ float AsD[32][256];   // 32 KB, A[m][k] duplicated: [k][2m],[2m+1]
    __shared__ float Bs [32][128];   // 16 KB
    int tid = threadIdx.x;
    int tx  = tid & 15;              // col group: cols tx*8 .. tx*8+7
    int ty  = tid >> 4;              // row group: rows ty*8 .. ty*8+7
    int m0  = blockIdx.x * 128;

    unsigned long long acc[8][4];
#pragma unroll
    for (int m = 0; m < 8; m++)
#pragma unroll
        for (int p = 0; p < 4; p++) acc[m][p] = 0ull;

    for (int k0 = 0; k0 < DIM; k0 += 32) {
        // A tile (1024 float4 loads, duplicated stores)
#pragma unroll
        for (int l = 0; l < 4; l++) {
            int f  = tid + l * 256;      // 0..1023
            int r  = f & 127;
            int kv = f >> 7;             // 0..7
            float4 v = make_float4(0.f, 0.f, 0.f, 0.f);
            int gr = m0 + r;
            if (gr < NN) v = *(const float4*)(A + (size_t)gr * DIM + k0 + kv * 4);
            *(float2*)&AsD[kv * 4 + 0][2 * r] = make_float2(v.x, v.x);
            *(float2*)&AsD[kv * 4 + 1][2 * r] = make_float2(v.y, v.y);
            *(float2*)&AsD[kv * 4 + 2][2 * r] = make_float2(v.z, v.z);
            *(float2*)&AsD[kv * 4 + 3][2 * r] = make_float2(v.w, v.w);
        }
        // B tile (1024 float4)
#pragma unroll
        for (int l = 0; l < 4; l++) {
            int f  = tid + l * 256;
            int k  = f >> 5;             // 0..31
            int cv = f & 31;
            *(float4*)&Bs[k][cv * 4] = *(const float4*)(B + (size_t)(k0 + k) * DIM + cv * 4);
        }
        __syncthreads();

#pragma unroll
        for (int k = 0; k < 32; k++) {
            ulonglong2 a01 = *(const ulonglong2*)&AsD[k][ty * 16 + 0];
            ulonglong2 a23 = *(const ulonglong2*)&AsD[k][ty * 16 + 4];
            ulonglong2 a45 = *(const ulonglong2*)&AsD[k][ty * 16 + 8];
            ulonglong2 a67 = *(const ulonglong2*)&AsD[k][ty * 16 + 12];
            ulonglong2 b01 = *(const ulonglong2*)&Bs[k][tx * 8 + 0];
            ulonglong2 b23 = *(const ulonglong2*)&Bs[k][tx * 8 + 4];
            unsigned long long av[8] = {a01.x, a01.y, a23.x, a23.y,
                                        a45.x, a45.y, a67.x, a67.y};
            unsigned long long bv[4] = {b01.x, b01.y, b23.x, b23.y};
#pragma unroll
            for (int m = 0; m < 8; m++)
#pragma unroll
                for (int p = 0; p < 4; p++)
                    asm("fma.rn.f32x2 %0, %1, %2, %0;"
                        : "+l"(acc[m][p]) : "l"(av[m]), "l"(bv[p]));
        }
        __syncthreads();
    }

    float bsum[8];
    if (bias) {
#pragma unroll
        for (int j = 0; j < 8; j++) {
            int c = tx * 8 + j;
            bsum[j] = bias[c] + bias[DIM + c] + bias[2 * DIM + c]
                    + bias[3 * DIM + c] + bias[4 * DIM + c];
        }
    }
#pragma unroll
    for (int m = 0; m < 8; m++) {
        int gr = m0 + ty * 8 + m;
        if (gr >= NN) continue;
        float* row = C + (size_t)gr * DIM + tx * 8;
        float r0 = lo32(acc[m][0]), r1 = hi32(acc[m][0]);
        float r2 = lo32(acc[m][1]), r3 = hi32(acc[m][1]);
        float r4 = lo32(acc[m][2]), r5 = hi32(acc[m][2]);
        float r6 = lo32(acc[m][3]), r7 = hi32(acc[m][3]);
        if (bias) {
            r0 += bsum[0]; r1 += bsum[1]; r2 += bsum[2]; r3 += bsum[3];
            r4 += bsum[4]; r5 += bsum[5]; r6 += bsum[6]; r7 += bsum[7];
        } else {
            float4 c0 = *(float4*)(row);
            float4 c1 = *(float4*)(row + 4);
            r0 += c0.x; r1 += c0.y; r2 += c0.z; r3 += c0.w;
            r4 += c1.x; r5 += c1.y; r6 += c1.z; r7 += c1.w;
        }
        *(float4*)(row)     = make_float4(r0, r1, r2, r3);
        *(float4*)(row + 4) = make_float4(r4, r5, r6, r7);
    }
}

// ---------------- relu store of graph-0 hidden -------------------------------
__global__ void k_relu_store() {
    int i = blockIdx.x * blockDim.x + threadIdx.x;   // over NN*32 float4s
    if (i >= NN * 32) return;
    float4 v = ((const float4*)g_acc)[i];
    v.x = fmaxf(v.x, 0.f); v.y = fmaxf(v.y, 0.f);
    v.z = fmaxf(v.z, 0.f); v.w = fmaxf(v.w, 0.f);
    ((float4*)g_h0)[i] = v;
}

// ---------------- fusion + classifier (FFMA2) --------------------------------
// BM=128, BN=64, BK=32, 256 threads, TM=8, TN=4 (2 packed pairs)
__global__ void __launch_bounds__(256, 2) k_final(const float* __restrict__ fw,
                                                  const float* __restrict__ Wc,
                                                  const float* __restrict__ bc,
                                                  float* __restrict__ out) {
    __shared__ float AsD[32][256];   // 32 KB (fused input, duplicated)
    __shared__ float Bs [32][64];    // 8 KB
    int tid = threadIdx.x;
    int tx  = tid & 15;              // cols tx*4 .. tx*4+3
    int ty  = tid >> 4;              // rows ty*8 .. ty*8+7
    int m0  = blockIdx.x * 128;

    float f0 = fw[0], f1 = fw[1];
    float mx = fmaxf(f0, f1);
    float e0 = __expf(f0 - mx), e1 = __expf(f1 - mx);
    float w0 = e0 / (e0 + e1), w1 = 1.0f - w0;

    unsigned long long acc[8][2];
#pragma unroll
    for (int m = 0; m < 8; m++) { acc[m][0] = 0ull; acc[m][1] = 0ull; }

    for (int k0 = 0; k0 < DIM; k0 += 32) {
        // fused A tile, duplicated
#pragma unroll
        for (int l = 0; l < 4; l++) {
            int f  = tid + l * 256;
            int r  = f & 127;
            int kv = f >> 7;
            float4 h = make_float4(0.f, 0.f, 0.f, 0.f);
            int gr = m0 + r;
            if (gr < NN) {
                size_t off = (size_t)gr * DIM + k0 + kv * 4;
                float4 h0 = *(const float4*)(g_h0 + off);
                float4 a  = *(const float4*)(g_acc + off);
                h.x = w0 * h0.x + w1 * fmaxf(a.x, 0.f);
                h.y = w0 * h0.y + w1 * fmaxf(a.y, 0.f);
                h.z = w0 * h0.z + w1 * fmaxf(a.z, 0.f);
                h.w = w0 * h0.w + w1 * fmaxf(a.w, 0.f);
            }
            *(float2*)&AsD[kv * 4 + 0][2 * r] = make_float2(h.x, h.x);
            *(float2*)&AsD[kv * 4 + 1][2 * r] = make_float2(h.y, h.y);
            *(float2*)&AsD[kv * 4 + 2][2 * r] = make_float2(h.z, h.z);
            *(float2*)&AsD[kv * 4 + 3][2 * r] = make_float2(h.w, h.w);
        }
        // Wc tile: 32x64 = 512 float4, 2 per thread
#pragma unroll
        for (int l = 0; l < 2; l++) {
            int f  = tid + l * 256;
            int k  = f >> 4;            // 0..31
            int cv = f & 15;            // 0..15
            *(float4*)&Bs[k][cv * 4] = *(const float4*)(Wc + (size_t)(k0 + k) * OUTD + cv * 4);
        }
        __syncthreads();

#pragma unroll
        for (int k = 0; k < 32; k++) {
            ulonglong2 a01 = *(const ulonglong2*)&AsD[k][ty * 16 + 0];
            ulonglong2 a23 = *(const ulonglong2*)&AsD[k][ty * 16 + 4];
            ulonglong2 a45 = *(const ulonglong2*)&AsD[k][ty * 16 + 8];
            ulonglong2 a67 = *(const ulonglong2*)&AsD[k][ty * 16 + 12];
            ulonglong2 b01 = *(const ulonglong2*)&Bs[k][tx * 4];
            unsigned long long av[8] = {a01.x, a01.y, a23.x, a23.y,
                                        a45.x, a45.y, a67.x, a67.y};
            unsigned long long bv[2] = {b01.x, b01.y};
#pragma unroll
            for (int m = 0; m < 8; m++)
#pragma unroll
                for (int p = 0; p < 2; p++)
                    asm("fma.rn.f32x2 %0, %1, %2, %0;"
                        : "+l"(acc[m][p]) : "l"(av[m]), "l"(bv[p]));
        }
        __syncthreads();
    }

    float4 bb = *(const float4*)(bc + tx * 4);
#pragma unroll
    for (int m = 0; m < 8; m++) {
        int gr = m0 + ty * 8 + m;
        if (gr >= NN) continue;
        float4 o;
        o.x = lo32(acc[m][0]) + bb.x;
        o.y = hi32(acc[m][0]) + bb.y;
        o.z = lo32(acc[m][1]) + bb.z;
        o.w = hi32(acc[m][1]) + bb.w;
        *(float4*)(out + (size_t)gr * OUTD + tx * 4) = o;
    }
}

// ---------------- host orchestration ---------------------------------------
extern "C" void kernel_launch(void* const* d_in, const int* in_sizes, int n_in,
                              void* d_out, int out_size) {
    const float* x      = (const float*)d_in[0];
    const int*   ei     = (const int*)d_in[1];
    const int*   gei    = (const int*)d_in[2];
    const float* w_orig = (const float*)d_in[3];
    const float* b_orig = (const float*)d_in[4];
    const float* w_aug  = (const float*)d_in[5];
    const float* b_aug  = (const float*)d_in[6];
    const float* fw     = (const float*)d_in[7];
    const float* clfw   = (const float*)d_in[8];
    const float* clfb   = (const float*)d_in[9];
    float*       out    = (float*)d_out;

    float *accp, *bufA, *bufB;
    cudaGetSymbolAddress((void**)&accp, g_acc);
    cudaGetSymbolAddress((void**)&bufA, g_bufA);
    cudaGetSymbolAddress((void**)&bufB, g_bufB);

    const int TB = 256;
    dim3 gN((NN + TB - 1) / TB);
    dim3 gE((EE + TB - 1) / TB);
    dim3 gV((NN * 32 + TB - 1) / TB);
    dim3 gP((NN * 32 + TB - 1) / TB);        // pull: 1 warp/node
    dim3 gG((NN + 127) / 128);               // GEMM blocks (782)

    for (int g = 0; g < 2; g++) {
        const int*   edges = g ? gei : ei;
        const float* W     = g ? w_aug : w_orig;
        const float* b     = g ? b_aug : b_orig;

        k_deg_init <<<gN, TB>>>();
        k_deg_count<<<gE, TB>>>(edges);
        k_deg_fin  <<<gN, TB>>>();

        k_scan1<<<NB_SCAN, 512>>>();
        k_scan2<<<1, 256>>>();
        k_scan3<<<gN, TB>>>();
        k_fill <<<gE, TB>>>(edges);

        k_gemm_acc<<<gG, TB>>>(x, W, accp, b);   // order-0 term, bias-init

        const float* src = x;
        float*       dst = bufA;
        for (int i = 1; i <= 4; i++) {
            k_pull<<<gP, TB>>>(src, dst);
            k_gemm_acc<<<gG, TB>>>(dst, W + (size_t)i * DIM * DIM, accp, nullptr);
            src = dst;
            dst = (dst == bufA) ? bufB : bufA;
        }

        if (g == 0) k_relu_store<<<gV, TB>>>();
    }

    k_final<<<gG, TB>>>(fw, clfw, clfb, out);
}